// round 6
// baseline (speedup 1.0000x reference)
#include <cuda_runtime.h>
#include <math.h>

#ifndef M_PI
#define M_PI 3.14159265358979323846
#endif

#define NBT 48
#define NC  64
#define NX  128
#define NY  128
#define NB  4
#define TIN 12
#define TOUT 4
#define UD  3
#define NDEPTH 4

typedef unsigned long long u64;

__device__ __forceinline__ u64 f2fma(u64 a, u64 b, u64 c) {
    u64 r; asm("fma.rn.f32x2 %0,%1,%2,%3;" : "=l"(r) : "l"(a), "l"(b), "l"(c)); return r;
}
__device__ __forceinline__ u64 f2sub(u64 a, u64 b) {
    u64 r; asm("sub.rn.f32x2 %0,%1,%2;" : "=l"(r) : "l"(a), "l"(b)); return r;
}
__device__ __forceinline__ u64 f2pack(float lo, float hi) {
    u64 r; asm("mov.b64 %0,{%1,%2};" : "=l"(r) : "f"(lo), "f"(hi)); return r;
}
__device__ __forceinline__ u64 f2dup(float v) { return f2pack(v, v); }
__device__ __forceinline__ float2 f2unpack(u64 a) {
    float2 r; asm("mov.b64 {%0,%1},%2;" : "=f"(r.x), "=f"(r.y) : "l"(a)); return r;
}
__device__ __forceinline__ u64 f2neg(u64 a) { return a ^ 0x8000000080000000ULL; }

// ---------------- scratch ---------------------------------------------------
__device__ float g_X [NBT*NC*NX*NY];
__device__ float g_Yf[NBT*NC*NX*32];
__device__ float g_Zr[NBT*NC*512];
__device__ float g_Zi[NBT*NC*512];
__device__ float g_Or[NBT*NC*512];
__device__ float g_Oi[NBT*NC*512];
__device__ float g_Xi[NBT*NC*NX*32];
__device__ float g_Wfy2[64*32*2];
__device__ float g_Wfx[128*32*2];
__device__ float g_Wix[32*128*2];
__device__ float g_Cy [16*128];
__device__ float g_Sy [16*128];

// ---------------- table init ------------------------------------------------
__global__ void init_tables_kernel() {
    int tid = blockIdx.x * blockDim.x + threadIdx.x;
    if (tid < 64*32) {
        int yp = tid >> 5, k = tid & 31;
        int kk = k & 15;
        for (int j = 0; j < 2; j++) {
            int y = 2*yp + j;
            double th = (2.0 * M_PI / 128.0) * (double)((kk * y) & 127);
            g_Wfy2[tid*2 + j] = (k < 16) ? (float)cos(th) : (float)(-sin(th));
        }
    }
    if (tid < 128*32) {
        int x = tid >> 5, m = tid & 31;
        int kx = (m < 16) ? m : (96 + m);
        double th = (2.0 * M_PI / 128.0) * (double)((kx * x) & 127);
        g_Wfx[2*tid]   = (float)cos(th);
        g_Wfx[2*tid+1] = (float)(-sin(th));
    }
    if (tid < 32*128) {
        int m = tid >> 7, x = tid & 127;
        int kx = (m < 16) ? m : (96 + m);
        double th = (2.0 * M_PI / 128.0) * (double)((kx * x) & 127);
        g_Wix[2*tid]   = (float)(cos(th) / 128.0);
        g_Wix[2*tid+1] = (float)(sin(th) / 128.0);
    }
    if (tid < 16*128) {
        int k = tid >> 7, y = tid & 127;
        if (k == 0) { g_Cy[tid] = 1.0f/128.0f; g_Sy[tid] = 0.0f; }
        else {
            double th = (2.0 * M_PI / 128.0) * (double)((k * y) & 127);
            g_Cy[tid] = (float)( 2.0 * cos(th) / 128.0);
            g_Sy[tid] = (float)(-2.0 * sin(th) / 128.0);
        }
    }
}

// ---------------- lifting ---------------------------------------------------
__global__ __launch_bounds__(256) void lift_kernel(
    const float* __restrict__ in, const float* __restrict__ Pw,
    const float* __restrict__ Pb)
{
    __shared__ float sPw[64*3];
    __shared__ float sPb[64];
    int tid = threadIdx.x;
    if (tid < 192) sPw[tid] = Pw[tid];
    if (tid < 64)  sPb[tid] = Pb[tid];
    __syncthreads();
    int idx = blockIdx.x * 256 + tid;
    int bt = idx >> 14, xy = idx & 16383;
    float a0 = in[(bt*3 + 0)*16384 + xy];
    float a1 = in[(bt*3 + 1)*16384 + xy];
    float a2 = in[(bt*3 + 2)*16384 + xy];
    float* dst = g_X + (size_t)bt * NC * 16384 + xy;
#pragma unroll
    for (int o = 0; o < 64; o++)
        dst[(size_t)o * 16384] = sPb[o] + sPw[o*3]*a0 + sPw[o*3+1]*a1 + sPw[o*3+2]*a2;
}

// ---------------- forward DFT over y ---------------------------------------
__global__ __launch_bounds__(256) void fwd_y_kernel() {
    __shared__ float sW2[4096];
    __shared__ float sR[8192];
    int tid = threadIdx.x;
    for (int i = tid; i < 4096; i += 256) sW2[i] = g_Wfy2[i];
    size_t rowBase = (size_t)blockIdx.x * 64;
    const float* src = g_X + rowBase * 128;
    for (int i = tid; i < 8192; i += 256) sR[i] = src[i];
    __syncthreads();
    int warp = tid >> 5, lane = tid & 31;
    const float* r0 = sR + warp * 8 * 128;
    const u64* w2 = (const u64*)sW2;
    u64 acc[8];
#pragma unroll
    for (int r = 0; r < 8; r++) acc[r] = 0ULL;
#pragma unroll 4
    for (int yq = 0; yq < 32; yq++) {
        u64 wA = w2[(2*yq)*32 + lane];
        u64 wB = w2[(2*yq+1)*32 + lane];
#pragma unroll
        for (int r = 0; r < 8; r++) {
            ulonglong2 q = *(const ulonglong2*)(r0 + r*128 + 4*yq);
            acc[r] = f2fma(q.x, wA, acc[r]);
            acc[r] = f2fma(q.y, wB, acc[r]);
        }
    }
#pragma unroll
    for (int r = 0; r < 8; r++) {
        float2 p = f2unpack(acc[r]);
        g_Yf[(rowBase + warp*8 + r)*32 + lane] = p.x + p.y;
    }
}

// ---------------- forward DFT over x (2 fields, global twiddles) -----------
// grid = 1536; block = 128; static smem 32KB
__global__ __launch_bounds__(128) void fwd_x_kernel() {
    __shared__ float sY0[4096], sY1[4096];
    int tid = threadIdx.x;
    const float* src = g_Yf + (size_t)blockIdx.x * 8192;
    for (int i = tid; i < 4096; i += 128) { sY0[i] = src[i]; sY1[i] = src[4096 + i]; }
    __syncthreads();
    int m   = tid >> 2;
    int ky0 = (tid & 3) * 4;
    const float2* wtab = (const float2*)g_Wfx;
    u64 rA[2][2], rB[2][2], ii[2][2];
#pragma unroll
    for (int f = 0; f < 2; f++)
#pragma unroll
        for (int p = 0; p < 2; p++) { rA[f][p] = 0ULL; rB[f][p] = 0ULL; ii[f][p] = 0ULL; }
#pragma unroll 2
    for (int x = 0; x < 128; x++) {
        float2 w = __ldg(wtab + x*32 + m);
        u64 wr2 = f2dup(w.x), wi2 = f2dup(w.y);
        u64 a00 = *(const u64*)(sY0 + x*32 + ky0);
        u64 b00 = *(const u64*)(sY0 + x*32 + 16 + ky0);
        u64 a01 = *(const u64*)(sY0 + x*32 + ky0 + 2);
        u64 b01 = *(const u64*)(sY0 + x*32 + 18 + ky0);
        u64 a10 = *(const u64*)(sY1 + x*32 + ky0);
        u64 b10 = *(const u64*)(sY1 + x*32 + 16 + ky0);
        u64 a11 = *(const u64*)(sY1 + x*32 + ky0 + 2);
        u64 b11 = *(const u64*)(sY1 + x*32 + 18 + ky0);
        rA[0][0] = f2fma(a00, wr2, rA[0][0]);  rB[0][0] = f2fma(b00, wi2, rB[0][0]);
        ii[0][0] = f2fma(a00, wi2, ii[0][0]);  ii[0][0] = f2fma(b00, wr2, ii[0][0]);
        rA[0][1] = f2fma(a01, wr2, rA[0][1]);  rB[0][1] = f2fma(b01, wi2, rB[0][1]);
        ii[0][1] = f2fma(a01, wi2, ii[0][1]);  ii[0][1] = f2fma(b01, wr2, ii[0][1]);
        rA[1][0] = f2fma(a10, wr2, rA[1][0]);  rB[1][0] = f2fma(b10, wi2, rB[1][0]);
        ii[1][0] = f2fma(a10, wi2, ii[1][0]);  ii[1][0] = f2fma(b10, wr2, ii[1][0]);
        rA[1][1] = f2fma(a11, wr2, rA[1][1]);  rB[1][1] = f2fma(b11, wi2, rB[1][1]);
        ii[1][1] = f2fma(a11, wi2, ii[1][1]);  ii[1][1] = f2fma(b11, wr2, ii[1][1]);
    }
#pragma unroll
    for (int f = 0; f < 2; f++) {
        size_t base = ((size_t)(blockIdx.x*2 + f))*512 + m*16 + ky0;
        *(u64*)(g_Zr + base)     = f2sub(rA[f][0], rB[f][0]);
        *(u64*)(g_Zr + base + 2) = f2sub(rA[f][1], rB[f][1]);
        *(u64*)(g_Zi + base)     = ii[f][0];
        *(u64*)(g_Zi + base + 2) = ii[f][1];
    }
}

// ---------------- per-mode channel mix -------------------------------------
__global__ __launch_bounds__(128) void mode_mix_kernel(
    const float* __restrict__ w1r, const float* __restrict__ w1i,
    const float* __restrict__ w2r, const float* __restrict__ w2i)
{
    int mp    = blockIdx.x * 128 + threadIdx.x;
    int mode0 = mp * 2;
    int half  = mode0 >> 8;
    int ml    = mode0 & 255;
    const float* Wr = half ? w2r : w1r;
    const float* Wi = half ? w2i : w1i;
    int bt0 = blockIdx.y * 4, o0 = blockIdx.z * 4;
    u64 aR[4][4], aI[4][4];
#pragma unroll
    for (int b = 0; b < 4; b++)
#pragma unroll
        for (int o = 0; o < 4; o++) { aR[b][o] = 0ULL; aI[b][o] = 0ULL; }

    for (int i = 0; i < 64; i++) {
        u64 zr[4], zi[4];
#pragma unroll
        for (int b = 0; b < 4; b++) {
            size_t zb = ((size_t)(bt0 + b)*64 + i)*512 + mode0;
            zr[b] = *(const u64*)(g_Zr + zb);
            zi[b] = *(const u64*)(g_Zi + zb);
        }
#pragma unroll
        for (int o = 0; o < 4; o++) {
            size_t wb = ((size_t)i*64 + (o0 + o))*256 + ml;
            u64 wr2  = *(const u64*)(Wr + wb);
            u64 wi2  = *(const u64*)(Wi + wb);
            u64 wi2n = f2neg(wi2);
#pragma unroll
            for (int b = 0; b < 4; b++) {
                aR[b][o] = f2fma(zr[b], wr2,  aR[b][o]);
                aR[b][o] = f2fma(zi[b], wi2n, aR[b][o]);
                aI[b][o] = f2fma(zr[b], wi2,  aI[b][o]);
                aI[b][o] = f2fma(zi[b], wr2,  aI[b][o]);
            }
        }
    }
#pragma unroll
    for (int b = 0; b < 4; b++)
#pragma unroll
        for (int o = 0; o < 4; o++) {
            size_t ob = ((size_t)(bt0 + b)*64 + (o0 + o))*512 + mode0;
            *(u64*)(g_Or + ob) = aR[b][o];
            *(u64*)(g_Oi + ob) = aI[b][o];
        }
}

// ---------------- inverse DFT over x ---------------------------------------
__global__ __launch_bounds__(256) void inv_x_kernel() {
    __shared__ float sOr[512], sOi[512];
    int tid = threadIdx.x;
    const float* srcr = g_Or + (size_t)blockIdx.x * 512;
    const float* srci = g_Oi + (size_t)blockIdx.x * 512;
    for (int i = tid; i < 512; i += 256) { sOr[i] = srcr[i]; sOi[i] = srci[i]; }
    __syncthreads();
    int x  = tid >> 1;
    int kb = (tid & 1) * 8;
    u64 arA[4], arB[4], ai[4];
#pragma unroll
    for (int j = 0; j < 4; j++) { arA[j] = 0ULL; arB[j] = 0ULL; ai[j] = 0ULL; }
#pragma unroll 4
    for (int m = 0; m < 32; m++) {
        float2 w = *(const float2*)(g_Wix + (m*128 + x)*2);
        u64 wr2 = f2dup(w.x), wi2 = f2dup(w.y);
#pragma unroll
        for (int j = 0; j < 4; j++) {
            u64 pr = *(const u64*)(sOr + m*16 + kb + 2*j);
            u64 pi = *(const u64*)(sOi + m*16 + kb + 2*j);
            arA[j] = f2fma(pr, wr2, arA[j]);
            arB[j] = f2fma(pi, wi2, arB[j]);
            ai[j]  = f2fma(pr, wi2, ai[j]);
            ai[j]  = f2fma(pi, wr2, ai[j]);
        }
    }
    float* dst = g_Xi + ((size_t)blockIdx.x * 128 + x) * 32;
#pragma unroll
    for (int j = 0; j < 4; j++) {
        *(u64*)(dst + kb + 2*j)      = f2sub(arA[j], arB[j]);
        *(u64*)(dst + 16 + kb + 2*j) = ai[j];
    }
}

// ---------------- fused tail: 8o x 8y register tiles, 128 threads ----------
// dyn smem 18880 floats = 75520 B; grid (128, 48)
__global__ __launch_bounds__(128) void fused_tail_kernel(
    const float* __restrict__ gctxd,
    const float* __restrict__ llw,
    const float* __restrict__ llb,
    const float* __restrict__ lng, const float* __restrict__ lnb)
{
    extern __shared__ float sm[];
    float* sXV  = sm;            // 8192 (c,y) -> later V (o,y)
    float* sLLT = sm + 8192;     // 4096 (c,o) transposed weights
    float* sXi  = sm + 12288;    // 2048 (o,32)
    float* sCy  = sm + 14336;    // 2048
    float* sSy  = sm + 16384;    // 2048
    float* sMu  = sm + 18432;    // 128
    float* sRs  = sm + 18560;    // 128
    float* sLNg = sm + 18688;    // 64
    float* sLNb = sm + 18752;    // 64
    float* sLLb = sm + 18816;    // 64

    int tid = threadIdx.x;
    int x   = blockIdx.x;
    int bt  = blockIdx.y;

    // phase 1: loads
    for (int i = tid; i < 8192; i += 128) {
        int c = i >> 7, y = i & 127;
        sXV[i] = g_X[(((size_t)bt*64 + c)*128 + x)*128 + y];
    }
    for (int i = tid; i < 4096; i += 128) {
        int c = i >> 6, o = i & 63;
        sLLT[i] = llw[o*64 + c];
    }
    for (int i = tid; i < 2048; i += 128) {
        int o = i >> 5, k = i & 31;
        sXi[i] = g_Xi[(((size_t)bt*64 + o)*128 + x)*32 + k];
    }
    for (int i = tid; i < 2048; i += 128) { sCy[i] = g_Cy[i]; sSy[i] = g_Sy[i]; }
    if (tid < 64) { sLNg[tid] = lng[tid]; sLNb[tid] = lnb[tid]; sLLb[tid] = llb[tid]; }
    __syncthreads();

    // phase 2: V[o][y] = LL @ X + inv-y(Xi)
    int og = tid >> 4, yg = tid & 15;
    int o0 = og * 8, y0 = yg * 8;
    u64 acc[8][4];
#pragma unroll
    for (int oo = 0; oo < 8; oo++)
#pragma unroll
        for (int p = 0; p < 4; p++) acc[oo][p] = 0ULL;

#pragma unroll 2
    for (int c = 0; c < 64; c++) {
        ulonglong2 xa = *(const ulonglong2*)(sXV + c*128 + y0);
        ulonglong2 xb = *(const ulonglong2*)(sXV + c*128 + y0 + 4);
        float4 w0 = *(const float4*)(sLLT + c*64 + o0);
        float4 w1 = *(const float4*)(sLLT + c*64 + o0 + 4);
        float wv[8] = {w0.x, w0.y, w0.z, w0.w, w1.x, w1.y, w1.z, w1.w};
#pragma unroll
        for (int oo = 0; oo < 8; oo++) {
            u64 w2 = f2dup(wv[oo]);
            acc[oo][0] = f2fma(xa.x, w2, acc[oo][0]);
            acc[oo][1] = f2fma(xa.y, w2, acc[oo][1]);
            acc[oo][2] = f2fma(xb.x, w2, acc[oo][2]);
            acc[oo][3] = f2fma(xb.y, w2, acc[oo][3]);
        }
    }
#pragma unroll
    for (int ky = 0; ky < 16; ky++) {
        ulonglong2 ca = *(const ulonglong2*)(sCy + ky*128 + y0);
        ulonglong2 cb = *(const ulonglong2*)(sCy + ky*128 + y0 + 4);
        ulonglong2 sa = *(const ulonglong2*)(sSy + ky*128 + y0);
        ulonglong2 sb = *(const ulonglong2*)(sSy + ky*128 + y0 + 4);
#pragma unroll
        for (int oo = 0; oo < 8; oo++) {
            u64 xr2 = f2dup(sXi[(o0 + oo)*32 + ky]);
            u64 xi2 = f2dup(sXi[(o0 + oo)*32 + 16 + ky]);
            acc[oo][0] = f2fma(xr2, ca.x, acc[oo][0]);
            acc[oo][0] = f2fma(xi2, sa.x, acc[oo][0]);
            acc[oo][1] = f2fma(xr2, ca.y, acc[oo][1]);
            acc[oo][1] = f2fma(xi2, sa.y, acc[oo][1]);
            acc[oo][2] = f2fma(xr2, cb.x, acc[oo][2]);
            acc[oo][2] = f2fma(xi2, sb.x, acc[oo][2]);
            acc[oo][3] = f2fma(xr2, cb.y, acc[oo][3]);
            acc[oo][3] = f2fma(xi2, sb.y, acc[oo][3]);
        }
    }
    __syncthreads();   // all sXV reads done; overwrite with V
#pragma unroll
    for (int oo = 0; oo < 8; oo++) {
        float b = sLLb[o0 + oo];
        float2 v0 = f2unpack(acc[oo][0]);
        float2 v1 = f2unpack(acc[oo][1]);
        float2 v2 = f2unpack(acc[oo][2]);
        float2 v3 = f2unpack(acc[oo][3]);
        *(float4*)(sXV + (o0 + oo)*128 + y0) =
            make_float4(v0.x + b, v0.y + b, v1.x + b, v1.y + b);
        *(float4*)(sXV + (o0 + oo)*128 + y0 + 4) =
            make_float4(v2.x + b, v2.y + b, v3.x + b, v3.y + b);
    }
    __syncthreads();

    // phase 3: LN stats, one thread per y
    {
        float s = 0.f, ss = 0.f;
        for (int o = 0; o < 64; o++) {
            float v = sXV[o*128 + tid];
            s += v; ss += v*v;
        }
        float mu = s * (1.0f/64.0f);
        float var = ss * (1.0f/64.0f) - mu*mu;
        sMu[tid] = mu;
        sRs[tid] = rsqrtf(var + 1e-5f);
    }
    __syncthreads();

    // phase 4: normalize + gelu + bilinear context + write back
    float cxf = x * 0.5f - 0.25f;
    int ix0 = (int)floorf(cxf);
    float wx1 = cxf - (float)ix0, wx0 = 1.0f - wx1;
    int cx0 = min(63, max(0, ix0));
    int cx1 = min(63, max(0, ix0 + 1));
    int y = tid;
    float cyf = y * 0.5f - 0.25f;
    int iy0 = (int)floorf(cyf);
    float wy1 = cyf - (float)iy0, wy0 = 1.0f - wy1;
    int cy0 = min(63, max(0, iy0));
    int cy1 = min(63, max(0, iy0 + 1));
    float mu = sMu[y], rs = sRs[y];

    for (int o = 0; o < 64; o++) {
        float v = sXV[o*128 + y];
        v = (v - mu) * rs * sLNg[o] + sLNb[o];
        v = 0.5f * v * (1.0f + erff(v * 0.70710678118654752440f));
        const float* gc = gctxd + ((size_t)bt*64 + o) * 4096;
        float g = wx0 * (wy0 * __ldg(gc + cx0*64 + cy0) + wy1 * __ldg(gc + cx0*64 + cy1))
                + wx1 * (wy0 * __ldg(gc + cx1*64 + cy0) + wy1 * __ldg(gc + cx1*64 + cy1));
        g_X[(((size_t)bt*64 + o)*128 + x)*128 + y] = v + g;
    }
}

// ---------------- temporal aggregation + projection ------------------------
__global__ __launch_bounds__(256) void head_kernel(
    const float* __restrict__ Wtw, const float* __restrict__ Wtb,
    const float* __restrict__ Qw,  const float* __restrict__ Qb,
    float* __restrict__ out)
{
    __shared__ float sWt[48], sWtb[4], sQ[192], sQb[3], sQS[3];
    int tid = threadIdx.x;
    if (tid < 48)  sWt[tid]  = Wtw[tid];
    if (tid < 4)   sWtb[tid] = Wtb[tid];
    if (tid < 192) sQ[tid]   = Qw[tid];
    if (tid < 3)   sQb[tid]  = Qb[tid];
    __syncthreads();
    if (tid < 3) {
        float s = 0.f;
        for (int c = 0; c < 64; c++) s += sQ[tid*64 + c];
        sQS[tid] = s;
    }
    __syncthreads();
    int idx = blockIdx.x * 256 + tid;
    int b = idx >> 14, xy = idx & 16383;
    float acc[TOUT][UD] = {};
    for (int c = 0; c < 64; c++) {
        float xv[TIN];
#pragma unroll
        for (int t = 0; t < TIN; t++)
            xv[t] = g_X[(((size_t)(b*TIN + t))*64 + c)*16384 + xy];
        float tt[TOUT];
#pragma unroll
        for (int o = 0; o < TOUT; o++) {
            float s = 0.f;
#pragma unroll
            for (int t = 0; t < TIN; t++) s += sWt[o*TIN + t] * xv[t];
            tt[o] = s;
        }
#pragma unroll
        for (int u = 0; u < UD; u++) {
            float q = sQ[u*64 + c];
#pragma unroll
            for (int o = 0; o < TOUT; o++) acc[o][u] += q * tt[o];
        }
    }
#pragma unroll
    for (int o = 0; o < TOUT; o++)
#pragma unroll
        for (int u = 0; u < UD; u++)
            out[(((size_t)b*TOUT + o)*UD + u)*16384 + xy] =
                acc[o][u] + sWtb[o]*sQS[u] + sQb[u];
}

// ---------------- launcher --------------------------------------------------
extern "C" void kernel_launch(void* const* d_in, const int* in_sizes, int n_in,
                              void* d_out, int out_size)
{
    const float* input = (const float*)d_in[0];
    const float* gctx  = (const float*)d_in[1];
    const float* P_w   = (const float*)d_in[2];
    const float* P_b   = (const float*)d_in[3];
    const float* Q_w   = (const float*)d_in[4];
    const float* Q_b   = (const float*)d_in[5];
    const float* Wt_w  = (const float*)d_in[6];
    const float* Wt_b  = (const float*)d_in[7];
    const float* w1r   = (const float*)d_in[8];
    const float* w1i   = (const float*)d_in[9];
    const float* w2r   = (const float*)d_in[10];
    const float* w2i   = (const float*)d_in[11];
    const float* ll_w  = (const float*)d_in[12];
    const float* ll_b  = (const float*)d_in[13];
    const float* ln_g  = (const float*)d_in[14];
    const float* ln_b  = (const float*)d_in[15];
    float* out = (float*)d_out;

    const int FUSED_SMEM = 18880 * 4;  // 75520 bytes
    cudaFuncSetAttribute(fused_tail_kernel,
                         cudaFuncAttributeMaxDynamicSharedMemorySize, FUSED_SMEM);

    init_tables_kernel<<<16, 256>>>();
    lift_kernel<<<3072, 256>>>(input, P_w, P_b);

    const size_t SPEC_D = (size_t)64*64*16*16;
    for (int d = 0; d < NDEPTH; d++) {
        fwd_y_kernel<<<6144, 256>>>();
        fwd_x_kernel<<<1536, 128>>>();
        dim3 g3(2, 12, 16);
        mode_mix_kernel<<<g3, 128>>>(w1r + d*SPEC_D, w1i + d*SPEC_D,
                                     w2r + d*SPEC_D, w2i + d*SPEC_D);
        inv_x_kernel<<<NBT*NC, 256>>>();
        dim3 g5(128, NBT);
        fused_tail_kernel<<<g5, 128, FUSED_SMEM>>>(
            gctx + (size_t)d*NBT*64*4096,
            ll_w + (size_t)d*4096, ll_b + d*64, ln_g + d*64, ln_b + d*64);
    }
    head_kernel<<<256, 256>>>(Wt_w, Wt_b, Q_w, Q_b, out);
}

// round 7
// speedup vs baseline: 1.1527x; 1.1527x over previous
#include <cuda_runtime.h>
#include <math.h>

#ifndef M_PI
#define M_PI 3.14159265358979323846
#endif

#define NBT 48
#define NC  64
#define NX  128
#define NY  128
#define NB  4
#define TIN 12
#define TOUT 4
#define UD  3
#define NDEPTH 4

typedef unsigned long long u64;

__device__ __forceinline__ u64 f2fma(u64 a, u64 b, u64 c) {
    u64 r; asm("fma.rn.f32x2 %0,%1,%2,%3;" : "=l"(r) : "l"(a), "l"(b), "l"(c)); return r;
}
__device__ __forceinline__ u64 f2sub(u64 a, u64 b) {
    u64 r; asm("sub.rn.f32x2 %0,%1,%2;" : "=l"(r) : "l"(a), "l"(b)); return r;
}
__device__ __forceinline__ u64 f2pack(float lo, float hi) {
    u64 r; asm("mov.b64 %0,{%1,%2};" : "=l"(r) : "f"(lo), "f"(hi)); return r;
}
__device__ __forceinline__ u64 f2dup(float v) { return f2pack(v, v); }
__device__ __forceinline__ float2 f2unpack(u64 a) {
    float2 r; asm("mov.b64 {%0,%1},%2;" : "=f"(r.x), "=f"(r.y) : "l"(a)); return r;
}
__device__ __forceinline__ u64 f2neg(u64 a) { return a ^ 0x8000000080000000ULL; }

// ---------------- scratch ---------------------------------------------------
__device__ float g_X [NBT*NC*NX*NY];
__device__ float g_Yf[NBT*NC*NX*32];
__device__ float g_Zr[NBT*NC*512];
__device__ float g_Zi[NBT*NC*512];
__device__ float g_Or[NBT*NC*512];
__device__ float g_Oi[NBT*NC*512];
__device__ float g_Xi[NBT*NC*NX*32];
__device__ float g_Wfy2[64*32*2];
__device__ float g_Wfx[128*32*2];
__device__ float g_Wix[32*128*2];
__device__ float g_Cy [16*128];
__device__ float g_Sy [16*128];

// ---------------- table init ------------------------------------------------
__global__ void init_tables_kernel() {
    int tid = blockIdx.x * blockDim.x + threadIdx.x;
    if (tid < 64*32) {
        int yp = tid >> 5, k = tid & 31;
        int kk = k & 15;
        for (int j = 0; j < 2; j++) {
            int y = 2*yp + j;
            double th = (2.0 * M_PI / 128.0) * (double)((kk * y) & 127);
            g_Wfy2[tid*2 + j] = (k < 16) ? (float)cos(th) : (float)(-sin(th));
        }
    }
    if (tid < 128*32) {
        int x = tid >> 5, m = tid & 31;
        int kx = (m < 16) ? m : (96 + m);
        double th = (2.0 * M_PI / 128.0) * (double)((kx * x) & 127);
        g_Wfx[2*tid]   = (float)cos(th);
        g_Wfx[2*tid+1] = (float)(-sin(th));
    }
    if (tid < 32*128) {
        int m = tid >> 7, x = tid & 127;
        int kx = (m < 16) ? m : (96 + m);
        double th = (2.0 * M_PI / 128.0) * (double)((kx * x) & 127);
        g_Wix[2*tid]   = (float)(cos(th) / 128.0);
        g_Wix[2*tid+1] = (float)(sin(th) / 128.0);
    }
    if (tid < 16*128) {
        int k = tid >> 7, y = tid & 127;
        if (k == 0) { g_Cy[tid] = 1.0f/128.0f; g_Sy[tid] = 0.0f; }
        else {
            double th = (2.0 * M_PI / 128.0) * (double)((k * y) & 127);
            g_Cy[tid] = (float)( 2.0 * cos(th) / 128.0);
            g_Sy[tid] = (float)(-2.0 * sin(th) / 128.0);
        }
    }
}

// ---------------- lifting ---------------------------------------------------
__global__ __launch_bounds__(256) void lift_kernel(
    const float* __restrict__ in, const float* __restrict__ Pw,
    const float* __restrict__ Pb)
{
    __shared__ float sPw[64*3];
    __shared__ float sPb[64];
    int tid = threadIdx.x;
    if (tid < 192) sPw[tid] = Pw[tid];
    if (tid < 64)  sPb[tid] = Pb[tid];
    __syncthreads();
    int idx = blockIdx.x * 256 + tid;
    int bt = idx >> 14, xy = idx & 16383;
    float a0 = in[(bt*3 + 0)*16384 + xy];
    float a1 = in[(bt*3 + 1)*16384 + xy];
    float a2 = in[(bt*3 + 2)*16384 + xy];
    float* dst = g_X + (size_t)bt * NC * 16384 + xy;
#pragma unroll
    for (int o = 0; o < 64; o++)
        dst[(size_t)o * 16384] = sPb[o] + sPw[o*3]*a0 + sPw[o*3+1]*a1 + sPw[o*3+2]*a2;
}

// ---------------- forward DFT over y (depth 0 only) ------------------------
__global__ __launch_bounds__(256) void fwd_y_kernel() {
    __shared__ float sW2[4096];
    __shared__ float sR[8192];
    int tid = threadIdx.x;
    for (int i = tid; i < 4096; i += 256) sW2[i] = g_Wfy2[i];
    size_t rowBase = (size_t)blockIdx.x * 64;
    const float* src = g_X + rowBase * 128;
    for (int i = tid; i < 8192; i += 256) sR[i] = src[i];
    __syncthreads();
    int warp = tid >> 5, lane = tid & 31;
    const float* r0 = sR + warp * 8 * 128;
    const u64* w2 = (const u64*)sW2;
    u64 acc[8];
#pragma unroll
    for (int r = 0; r < 8; r++) acc[r] = 0ULL;
#pragma unroll 4
    for (int yq = 0; yq < 32; yq++) {
        u64 wA = w2[(2*yq)*32 + lane];
        u64 wB = w2[(2*yq+1)*32 + lane];
#pragma unroll
        for (int r = 0; r < 8; r++) {
            ulonglong2 q = *(const ulonglong2*)(r0 + r*128 + 4*yq);
            acc[r] = f2fma(q.x, wA, acc[r]);
            acc[r] = f2fma(q.y, wB, acc[r]);
        }
    }
#pragma unroll
    for (int r = 0; r < 8; r++) {
        float2 p = f2unpack(acc[r]);
        g_Yf[(rowBase + warp*8 + r)*32 + lane] = p.x + p.y;
    }
}

// ---------------- forward DFT over x (R6 version, 72us) --------------------
__global__ __launch_bounds__(128) void fwd_x_kernel() {
    __shared__ float sY0[4096], sY1[4096];
    int tid = threadIdx.x;
    const float* src = g_Yf + (size_t)blockIdx.x * 8192;
    for (int i = tid; i < 4096; i += 128) { sY0[i] = src[i]; sY1[i] = src[4096 + i]; }
    __syncthreads();
    int m   = tid >> 2;
    int ky0 = (tid & 3) * 4;
    const float2* wtab = (const float2*)g_Wfx;
    u64 rA[2][2], rB[2][2], ii[2][2];
#pragma unroll
    for (int f = 0; f < 2; f++)
#pragma unroll
        for (int p = 0; p < 2; p++) { rA[f][p] = 0ULL; rB[f][p] = 0ULL; ii[f][p] = 0ULL; }
#pragma unroll 2
    for (int x = 0; x < 128; x++) {
        float2 w = __ldg(wtab + x*32 + m);
        u64 wr2 = f2dup(w.x), wi2 = f2dup(w.y);
        u64 a00 = *(const u64*)(sY0 + x*32 + ky0);
        u64 b00 = *(const u64*)(sY0 + x*32 + 16 + ky0);
        u64 a01 = *(const u64*)(sY0 + x*32 + ky0 + 2);
        u64 b01 = *(const u64*)(sY0 + x*32 + 18 + ky0);
        u64 a10 = *(const u64*)(sY1 + x*32 + ky0);
        u64 b10 = *(const u64*)(sY1 + x*32 + 16 + ky0);
        u64 a11 = *(const u64*)(sY1 + x*32 + ky0 + 2);
        u64 b11 = *(const u64*)(sY1 + x*32 + 18 + ky0);
        rA[0][0] = f2fma(a00, wr2, rA[0][0]);  rB[0][0] = f2fma(b00, wi2, rB[0][0]);
        ii[0][0] = f2fma(a00, wi2, ii[0][0]);  ii[0][0] = f2fma(b00, wr2, ii[0][0]);
        rA[0][1] = f2fma(a01, wr2, rA[0][1]);  rB[0][1] = f2fma(b01, wi2, rB[0][1]);
        ii[0][1] = f2fma(a01, wi2, ii[0][1]);  ii[0][1] = f2fma(b01, wr2, ii[0][1]);
        rA[1][0] = f2fma(a10, wr2, rA[1][0]);  rB[1][0] = f2fma(b10, wi2, rB[1][0]);
        ii[1][0] = f2fma(a10, wi2, ii[1][0]);  ii[1][0] = f2fma(b10, wr2, ii[1][0]);
        rA[1][1] = f2fma(a11, wr2, rA[1][1]);  rB[1][1] = f2fma(b11, wi2, rB[1][1]);
        ii[1][1] = f2fma(a11, wi2, ii[1][1]);  ii[1][1] = f2fma(b11, wr2, ii[1][1]);
    }
#pragma unroll
    for (int f = 0; f < 2; f++) {
        size_t base = ((size_t)(blockIdx.x*2 + f))*512 + m*16 + ky0;
        *(u64*)(g_Zr + base)     = f2sub(rA[f][0], rB[f][0]);
        *(u64*)(g_Zr + base + 2) = f2sub(rA[f][1], rB[f][1]);
        *(u64*)(g_Zi + base)     = ii[f][0];
        *(u64*)(g_Zi + base + 2) = ii[f][1];
    }
}

// ---------------- per-mode channel mix -------------------------------------
__global__ __launch_bounds__(128) void mode_mix_kernel(
    const float* __restrict__ w1r, const float* __restrict__ w1i,
    const float* __restrict__ w2r, const float* __restrict__ w2i)
{
    int mp    = blockIdx.x * 128 + threadIdx.x;
    int mode0 = mp * 2;
    int half  = mode0 >> 8;
    int ml    = mode0 & 255;
    const float* Wr = half ? w2r : w1r;
    const float* Wi = half ? w2i : w1i;
    int bt0 = blockIdx.y * 4, o0 = blockIdx.z * 4;
    u64 aR[4][4], aI[4][4];
#pragma unroll
    for (int b = 0; b < 4; b++)
#pragma unroll
        for (int o = 0; o < 4; o++) { aR[b][o] = 0ULL; aI[b][o] = 0ULL; }

    for (int i = 0; i < 64; i++) {
        u64 zr[4], zi[4];
#pragma unroll
        for (int b = 0; b < 4; b++) {
            size_t zb = ((size_t)(bt0 + b)*64 + i)*512 + mode0;
            zr[b] = *(const u64*)(g_Zr + zb);
            zi[b] = *(const u64*)(g_Zi + zb);
        }
#pragma unroll
        for (int o = 0; o < 4; o++) {
            size_t wb = ((size_t)i*64 + (o0 + o))*256 + ml;
            u64 wr2  = *(const u64*)(Wr + wb);
            u64 wi2  = *(const u64*)(Wi + wb);
            u64 wi2n = f2neg(wi2);
#pragma unroll
            for (int b = 0; b < 4; b++) {
                aR[b][o] = f2fma(zr[b], wr2,  aR[b][o]);
                aR[b][o] = f2fma(zi[b], wi2n, aR[b][o]);
                aI[b][o] = f2fma(zr[b], wi2,  aI[b][o]);
                aI[b][o] = f2fma(zi[b], wr2,  aI[b][o]);
            }
        }
    }
#pragma unroll
    for (int b = 0; b < 4; b++)
#pragma unroll
        for (int o = 0; o < 4; o++) {
            size_t ob = ((size_t)(bt0 + b)*64 + (o0 + o))*512 + mode0;
            *(u64*)(g_Or + ob) = aR[b][o];
            *(u64*)(g_Oi + ob) = aI[b][o];
        }
}

// ---------------- inverse DFT over x ---------------------------------------
__global__ __launch_bounds__(256) void inv_x_kernel() {
    __shared__ float sOr[512], sOi[512];
    int tid = threadIdx.x;
    const float* srcr = g_Or + (size_t)blockIdx.x * 512;
    const float* srci = g_Oi + (size_t)blockIdx.x * 512;
    for (int i = tid; i < 512; i += 256) { sOr[i] = srcr[i]; sOi[i] = srci[i]; }
    __syncthreads();
    int x  = tid >> 1;
    int kb = (tid & 1) * 8;
    u64 arA[4], arB[4], ai[4];
#pragma unroll
    for (int j = 0; j < 4; j++) { arA[j] = 0ULL; arB[j] = 0ULL; ai[j] = 0ULL; }
#pragma unroll 4
    for (int m = 0; m < 32; m++) {
        float2 w = *(const float2*)(g_Wix + (m*128 + x)*2);
        u64 wr2 = f2dup(w.x), wi2 = f2dup(w.y);
#pragma unroll
        for (int j = 0; j < 4; j++) {
            u64 pr = *(const u64*)(sOr + m*16 + kb + 2*j);
            u64 pi = *(const u64*)(sOi + m*16 + kb + 2*j);
            arA[j] = f2fma(pr, wr2, arA[j]);
            arB[j] = f2fma(pi, wi2, arB[j]);
            ai[j]  = f2fma(pr, wi2, ai[j]);
            ai[j]  = f2fma(pi, wr2, ai[j]);
        }
    }
    float* dst = g_Xi + ((size_t)blockIdx.x * 128 + x) * 32;
#pragma unroll
    for (int j = 0; j < 4; j++) {
        *(u64*)(dst + kb + 2*j)      = f2sub(arA[j], arB[j]);
        *(u64*)(dst + 16 + kb + 2*j) = ai[j];
    }
}

// ---------------- fused tail (R5 base + ctx staging + fused y-DFT) ---------
// 256 threads; dyn smem 25536 floats = 102144 B; grid (128, 48)
__global__ __launch_bounds__(256) void fused_tail_kernel(
    const float* __restrict__ gctxd,
    const float* __restrict__ llw,
    const float* __restrict__ llb,
    const float* __restrict__ lng, const float* __restrict__ lnb,
    int write_yf)
{
    extern __shared__ float sm[];
    float* sXV  = sm;                      // 8192 : X (c,y) -> V (o,y) -> final (o,y)
    u64*   sLLd = (u64*)(sm + 8192);       // 4096 u64 : dup'd ll weights (dead after ph2)
    float* sCtx = sm + 8192;               // alias: ctx rows (o,2,64) after phase 2
    u64*   sXid = (u64*)(sm + 16384);      // 2048 u64 : dup'd inv-x spectrum
    float* sCy  = sm + 20480;
    float* sSy  = sm + 22528;
    float* sPS  = sm + 24576;
    float* sPQ  = sm + 24832;
    float* sMu  = sm + 25088;
    float* sRs  = sm + 25216;
    float* sLNg = sm + 25344;
    float* sLNb = sm + 25408;
    float* sLLb = sm + 25472;

    int tid = threadIdx.x;
    int x   = blockIdx.x;
    int bt  = blockIdx.y;

    // block-uniform x interpolation
    float cxf = x * 0.5f - 0.25f;
    int ix0 = (int)floorf(cxf);
    float wx1 = cxf - (float)ix0, wx0 = 1.0f - wx1;
    int cx0 = min(63, max(0, ix0));
    int cx1 = min(63, max(0, ix0 + 1));

    // phase 1: loads (+ dup'd operand tables)
    for (int i = tid; i < 8192; i += 256) {
        int c = i >> 7, y = i & 127;
        sXV[i] = g_X[(((size_t)bt*64 + c)*128 + x)*128 + y];
    }
    for (int i = tid; i < 4096; i += 256) sLLd[i] = f2dup(llw[i]);
    for (int i = tid; i < 2048; i += 256) {
        int o = i >> 5, k = i & 31;
        sXid[i] = f2dup(g_Xi[(((size_t)bt*64 + o)*128 + x)*32 + k]);
    }
    for (int i = tid; i < 2048; i += 256) { sCy[i] = g_Cy[i]; sSy[i] = g_Sy[i]; }
    if (tid < 64) { sLNg[tid] = lng[tid]; sLNb[tid] = lnb[tid]; sLLb[tid] = llb[tid]; }
    __syncthreads();

    // phase 2: V[o][y] = LL @ X + inv-y(Xi)
    int o0  = (tid >> 5) * 8;
    int tx4 = (tid & 31) * 4;
    u64 acc0[8], acc1[8];
#pragma unroll
    for (int oo = 0; oo < 8; oo++) { acc0[oo] = 0ULL; acc1[oo] = 0ULL; }

#pragma unroll 2
    for (int c = 0; c < 64; c++) {
        ulonglong2 xv = *(const ulonglong2*)(sXV + c*128 + tx4);
#pragma unroll
        for (int oo = 0; oo < 8; oo++) {
            u64 w2 = sLLd[(o0 + oo)*64 + c];
            acc0[oo] = f2fma(xv.x, w2, acc0[oo]);
            acc1[oo] = f2fma(xv.y, w2, acc1[oo]);
        }
    }
#pragma unroll
    for (int ky = 0; ky < 16; ky++) {
        ulonglong2 cy = *(const ulonglong2*)(sCy + ky*128 + tx4);
        ulonglong2 sy = *(const ulonglong2*)(sSy + ky*128 + tx4);
#pragma unroll
        for (int oo = 0; oo < 8; oo++) {
            u64 xr2 = sXid[(o0 + oo)*32 + ky];
            u64 xi2 = sXid[(o0 + oo)*32 + 16 + ky];
            acc0[oo] = f2fma(xr2, cy.x, acc0[oo]);
            acc0[oo] = f2fma(xi2, sy.x, acc0[oo]);
            acc1[oo] = f2fma(xr2, cy.y, acc1[oo]);
            acc1[oo] = f2fma(xi2, sy.y, acc1[oo]);
        }
    }
    __syncthreads();   // sXV reads + sLLd reads done
    // write V into sXV; concurrently stage ctx rows into sCtx (aliases sLLd)
#pragma unroll
    for (int oo = 0; oo < 8; oo++) {
        float b = sLLb[o0 + oo];
        float2 v0 = f2unpack(acc0[oo]);
        float2 v1 = f2unpack(acc1[oo]);
        *(float4*)(sXV + (o0 + oo)*128 + tx4) =
            make_float4(v0.x + b, v0.y + b, v1.x + b, v1.y + b);
    }
    for (int i = tid; i < 8192; i += 256) {
        int o = i >> 7, rest = i & 127;
        int j = rest >> 6, c = rest & 63;
        int cx = j ? cx1 : cx0;
        sCtx[i] = gctxd[((size_t)bt*64 + o)*4096 + cx*64 + c];
    }
    __syncthreads();

    // phase 3: layernorm stats per y (two halves)
    {
        int yy = tid & 127, oh = tid >> 7;
        float s = 0.f, ss = 0.f;
        int ob = oh * 32;
        for (int o = ob; o < ob + 32; o++) {
            float v = sXV[o*128 + yy];
            s += v; ss += v*v;
        }
        sPS[tid] = s; sPQ[tid] = ss;
    }
    __syncthreads();
    if (tid < 128) {
        float s = sPS[tid] + sPS[128 + tid];
        float q = sPQ[tid] + sPQ[128 + tid];
        float mu = s * (1.0f/64.0f);
        float var = q * (1.0f/64.0f) - mu*mu;
        sMu[tid] = mu;
        sRs[tid] = rsqrtf(var + 1e-5f);
    }
    __syncthreads();

    // phase 4: normalize + gelu + ctx (from smem) ; write g_X and sXV
    int y = tid & 127;
    float cyf = y * 0.5f - 0.25f;
    int iy0 = (int)floorf(cyf);
    float wy1 = cyf - (float)iy0, wy0 = 1.0f - wy1;
    int cy0 = min(63, max(0, iy0));
    int cy1 = min(63, max(0, iy0 + 1));
    float mu = sMu[y], rs = sRs[y];

    for (int j = 0; j < 32; j++) {
        int idx = j * 256 + tid;
        int o = idx >> 7;
        float v = sXV[o*128 + y];
        v = (v - mu) * rs * sLNg[o] + sLNb[o];
        v = 0.5f * v * (1.0f + erff(v * 0.70710678118654752440f));
        const float* cr = sCtx + o*128;
        float g = wx0 * (wy0 * cr[cy0] + wy1 * cr[cy1])
                + wx1 * (wy0 * cr[64 + cy0] + wy1 * cr[64 + cy1]);
        float fin = v + g;
        g_X[(((size_t)bt*64 + o)*128 + x)*128 + y] = fin;
        sXV[o*128 + y] = fin;     // unique (o,y) per thread: safe in-place
    }

    // phase 5: fused y-DFT of final values -> g_Yf (next depth's fwd_x input)
    if (write_yf) {
        __syncthreads();
        int warp = tid >> 5, lane = tid & 31;
        const u64* w2 = (const u64*)g_Wfy2;
        int ob = warp * 8;
        u64 acc[8];
#pragma unroll
        for (int r = 0; r < 8; r++) acc[r] = 0ULL;
#pragma unroll 4
        for (int yp = 0; yp < 64; yp++) {
            u64 w = __ldg(w2 + yp*32 + lane);
#pragma unroll
            for (int r = 0; r < 8; r++) {
                u64 v2 = *(const u64*)(sXV + (ob + r)*128 + 2*yp);
                acc[r] = f2fma(v2, w, acc[r]);
            }
        }
#pragma unroll
        for (int r = 0; r < 8; r++) {
            float2 p = f2unpack(acc[r]);
            g_Yf[(((size_t)bt*64 + ob + r)*128 + x)*32 + lane] = p.x + p.y;
        }
    }
}

// ---------------- temporal aggregation + projection ------------------------
__global__ __launch_bounds__(256) void head_kernel(
    const float* __restrict__ Wtw, const float* __restrict__ Wtb,
    const float* __restrict__ Qw,  const float* __restrict__ Qb,
    float* __restrict__ out)
{
    __shared__ float sWt[48], sWtb[4], sQ[192], sQb[3], sQS[3];
    int tid = threadIdx.x;
    if (tid < 48)  sWt[tid]  = Wtw[tid];
    if (tid < 4)   sWtb[tid] = Wtb[tid];
    if (tid < 192) sQ[tid]   = Qw[tid];
    if (tid < 3)   sQb[tid]  = Qb[tid];
    __syncthreads();
    if (tid < 3) {
        float s = 0.f;
        for (int c = 0; c < 64; c++) s += sQ[tid*64 + c];
        sQS[tid] = s;
    }
    __syncthreads();
    int idx = blockIdx.x * 256 + tid;
    int b = idx >> 14, xy = idx & 16383;
    float acc[TOUT][UD] = {};
    for (int c = 0; c < 64; c++) {
        float xv[TIN];
#pragma unroll
        for (int t = 0; t < TIN; t++)
            xv[t] = g_X[(((size_t)(b*TIN + t))*64 + c)*16384 + xy];
        float tt[TOUT];
#pragma unroll
        for (int o = 0; o < TOUT; o++) {
            float s = 0.f;
#pragma unroll
            for (int t = 0; t < TIN; t++) s += sWt[o*TIN + t] * xv[t];
            tt[o] = s;
        }
#pragma unroll
        for (int u = 0; u < UD; u++) {
            float q = sQ[u*64 + c];
#pragma unroll
            for (int o = 0; o < TOUT; o++) acc[o][u] += q * tt[o];
        }
    }
#pragma unroll
    for (int o = 0; o < TOUT; o++)
#pragma unroll
        for (int u = 0; u < UD; u++)
            out[(((size_t)b*TOUT + o)*UD + u)*16384 + xy] =
                acc[o][u] + sWtb[o]*sQS[u] + sQb[u];
}

// ---------------- launcher --------------------------------------------------
extern "C" void kernel_launch(void* const* d_in, const int* in_sizes, int n_in,
                              void* d_out, int out_size)
{
    const float* input = (const float*)d_in[0];
    const float* gctx  = (const float*)d_in[1];
    const float* P_w   = (const float*)d_in[2];
    const float* P_b   = (const float*)d_in[3];
    const float* Q_w   = (const float*)d_in[4];
    const float* Q_b   = (const float*)d_in[5];
    const float* Wt_w  = (const float*)d_in[6];
    const float* Wt_b  = (const float*)d_in[7];
    const float* w1r   = (const float*)d_in[8];
    const float* w1i   = (const float*)d_in[9];
    const float* w2r   = (const float*)d_in[10];
    const float* w2i   = (const float*)d_in[11];
    const float* ll_w  = (const float*)d_in[12];
    const float* ll_b  = (const float*)d_in[13];
    const float* ln_g  = (const float*)d_in[14];
    const float* ln_b  = (const float*)d_in[15];
    float* out = (float*)d_out;

    const int FUSED_SMEM = 25536 * 4;  // 102144 bytes
    cudaFuncSetAttribute(fused_tail_kernel,
                         cudaFuncAttributeMaxDynamicSharedMemorySize, FUSED_SMEM);

    init_tables_kernel<<<16, 256>>>();
    lift_kernel<<<3072, 256>>>(input, P_w, P_b);
    fwd_y_kernel<<<6144, 256>>>();          // depth 0 only

    const size_t SPEC_D = (size_t)64*64*16*16;
    for (int d = 0; d < NDEPTH; d++) {
        fwd_x_kernel<<<1536, 128>>>();
        dim3 g3(2, 12, 16);
        mode_mix_kernel<<<g3, 128>>>(w1r + d*SPEC_D, w1i + d*SPEC_D,
                                     w2r + d*SPEC_D, w2i + d*SPEC_D);
        inv_x_kernel<<<NBT*NC, 256>>>();
        dim3 g5(128, NBT);
        fused_tail_kernel<<<g5, 256, FUSED_SMEM>>>(
            gctx + (size_t)d*NBT*64*4096,
            ll_w + (size_t)d*4096, ll_b + d*64, ln_g + d*64, ln_b + d*64,
            (d < NDEPTH-1) ? 1 : 0);
    }
    head_kernel<<<256, 256>>>(Wt_w, Wt_b, Q_w, Q_b, out);
}